// round 10
// baseline (speedup 1.0000x reference)
#include <cuda_runtime.h>

// SparseBiasDiagUnfolder — one wave, grid (146, 2) x 448 threads
// (2 CTAs/SM, 28 warps/SM resident), 2 window-rows per warp,
// div-free, compare-free, fully 32-bit index math.
//
//   adj: (B=2, N=2048, N=2048, F=16) fp32; starts 0,4,...,2040 (511);
//   out (B, 511, 56*16).
//
// blockIdx.y = b (batch) -> no runtime b/s decompose at all.
// Per b: 511 starts x 8 rows = 4088 rows, 2 rows/warp -> 2044 warps
// = 146 blocks x 14 warps exactly. Warp w covers rows [2w, 2w+2),
// sharing s = w>>2, ii_base = (w&3)*2. Each row is a 512B contiguous
// run in adj: lane l loads float4 base+l -> 2 independent fully-
// coalesced LDG.128 batched up front. Stores: 28 active lanes/row
// write a contiguous 448B run (diagonal dropped, repacked).

namespace {
constexpr int N        = 2048;
constexpr int NSTARTS  = 511;
constexpr int WARPS_PER_BLOCK = 14;
constexpr int THREADS  = WARPS_PER_BLOCK * 32;   // 448
constexpr int BLOCKS_X = 146;                    // 2044 warps per batch
}

__global__ void __launch_bounds__(THREADS)
sparse_diag_unfold_kernel(const float4* __restrict__ adj, float4* __restrict__ out)
{
    const unsigned gt   = blockIdx.x * THREADS + threadIdx.x;
    const unsigned w    = gt >> 5;                 // 0..2043 (within batch)
    const unsigned lane = gt & 31;
    const unsigned b    = blockIdx.y;              // batch: no decompose

    const unsigned s       = w >> 2;               // 0..510
    const unsigned ii_base = (w & 3) * 2;          // 0,2,4,6

    // 32-bit float4 base index of row (b, s, ii_base):
    //   b*N*N*4 + s*(N+1)*16 + ii_base*N*4 + lane   (max ~2^25)
    const unsigned base0 = b * (N * N * 4u)
                         + s * ((N + 1) * 16u)
                         + ii_base * (N * 4u)
                         + lane;

    const unsigned jj = lane >> 2;
    const unsigned v  = lane & 3;

    // 2 independent coalesced 512B loads, batched (MLP_p1 = 2).
    float4 vals[2];
    #pragma unroll
    for (int k = 0; k < 2; k++)
        vals[k] = adj[base0 + (unsigned)k * (N * 4u)];

    const unsigned out_base = (b * NSTARTS + s) * (56u * 4u);
    #pragma unroll
    for (int k = 0; k < 2; k++) {
        const unsigned ii = ii_base + k;
        if (jj != ii) {
            const unsigned pos = ii * 7u + jj - (jj > ii);   // 0..55
            out[out_base + pos * 4u + v] = vals[k];
        }
    }
}

extern "C" void kernel_launch(void* const* d_in, const int* in_sizes, int n_in,
                              void* d_out, int out_size)
{
    const float4* adj = (const float4*)d_in[0];
    float4* out = (float4*)d_out;
    dim3 grid(BLOCKS_X, 2);
    sparse_diag_unfold_kernel<<<grid, THREADS>>>(adj, out);
}